// round 7
// baseline (speedup 1.0000x reference)
#include <cuda_runtime.h>
#include <cuda_bf16.h>
#include <math.h>
#include <stdint.h>

#define N_WAY     100
#define K_SHOT    10
#define N_SUPPORT 1000
#define N_QUERY   8192
#define F_IN      4096
#define D_EMB     1024
#define EPS_F     1e-6f

#define M_TOT     9216   // 8192 query rows + 1000 support + 24 pad

// ---------------- scratch (static device globals; no allocations) ----------
__device__ __nv_bfloat16 g_Ahi[(size_t)M_TOT * F_IN];
__device__ __nv_bfloat16 g_Alo[(size_t)M_TOT * F_IN];
__device__ __nv_bfloat16 g_Wthi[(size_t)D_EMB * F_IN];
__device__ __nv_bfloat16 g_Wtlo[(size_t)D_EMB * F_IN];
__device__ float g_Z[(size_t)M_TOT * D_EMB];
__device__ float g_proto[128 * D_EMB];
__device__ float g_p2[128];
__device__ float g_ps[128];
__device__ float g_q2[N_QUERY];
__device__ float g_qs[N_QUERY];

// ======================= portable PTX helpers ==============================
__device__ __forceinline__ uint32_t smem_u32(const void* p) {
    uint32_t a;
    asm("{ .reg .u64 t; cvta.to.shared.u64 t, %1; cvt.u32.u64 %0, t; }"
        : "=r"(a) : "l"(p));
    return a;
}
__device__ __forceinline__ void cp_async16(uint32_t dst, const void* src) {
    asm volatile("cp.async.cg.shared.global [%0], [%1], 16;"
                 :: "r"(dst), "l"(src) : "memory");
}
__device__ __forceinline__ void cp_commit() {
    asm volatile("cp.async.commit_group;" ::: "memory");
}
__device__ __forceinline__ void cp_wait1() {
    asm volatile("cp.async.wait_group 1;" ::: "memory");
}
__device__ __forceinline__ void ldmx4(uint32_t* r, uint32_t addr) {
    asm volatile("ldmatrix.sync.aligned.m8n8.x4.shared.b16 {%0,%1,%2,%3}, [%4];"
                 : "=r"(r[0]), "=r"(r[1]), "=r"(r[2]), "=r"(r[3]) : "r"(addr));
}
__device__ __forceinline__ void mma_bf16(float* c, const uint32_t* a, const uint32_t* b) {
    asm volatile(
        "mma.sync.aligned.m16n8k16.row.col.f32.bf16.bf16.f32 "
        "{%0,%1,%2,%3}, {%4,%5,%6,%7}, {%8,%9}, {%0,%1,%2,%3};"
        : "+f"(c[0]), "+f"(c[1]), "+f"(c[2]), "+f"(c[3])
        : "r"(a[0]), "r"(a[1]), "r"(a[2]), "r"(a[3]), "r"(b[0]), "r"(b[1]));
}

// =====================================================================
// Kernel A: split fp32 inputs into bf16 hi/lo
// =====================================================================
__global__ void convert_A(const float* __restrict__ q, const float* __restrict__ s)
{
    size_t i = (size_t)blockIdx.x * blockDim.x + threadIdx.x;
    const size_t total = (size_t)M_TOT * F_IN / 4;
    if (i >= total) return;
    const size_t row = i / (F_IN / 4);
    const size_t seg = i % (F_IN / 4);
    float4 v;
    if (row < N_QUERY)                  v = *(const float4*)(q + row * F_IN + seg * 4);
    else if (row < N_QUERY + N_SUPPORT) v = *(const float4*)(s + (row - N_QUERY) * F_IN + seg * 4);
    else                                v = make_float4(0.f, 0.f, 0.f, 0.f);

    float x[4] = {v.x, v.y, v.z, v.w};
    union B4 { __nv_bfloat16 b[4]; uint2 u; } uh, ul;
    #pragma unroll
    for (int j = 0; j < 4; j++) {
        __nv_bfloat16 h = __float2bfloat16_rn(x[j]);
        uh.b[j] = h;
        ul.b[j] = __float2bfloat16_rn(x[j] - __bfloat162float(h));
    }
    *(uint2*)(g_Ahi + i * 4) = uh.u;
    *(uint2*)(g_Alo + i * 4) = ul.u;
}

// =====================================================================
// Kernel B: transpose W [4096,1024] -> Wt hi/lo [1024,4096] bf16
// =====================================================================
__global__ void convert_W(const float* __restrict__ W)
{
    __shared__ __nv_bfloat16 th[32][33];
    __shared__ __nv_bfloat16 tl[32][33];
    const int k0 = blockIdx.x * 32, n0 = blockIdx.y * 32;
    const int tx = threadIdx.x, ty = threadIdx.y;   // (32, 8)
    #pragma unroll
    for (int i = 0; i < 4; i++) {
        const int kk = ty + i * 8;
        float x = W[(size_t)(k0 + kk) * D_EMB + n0 + tx];
        __nv_bfloat16 h = __float2bfloat16_rn(x);
        th[kk][tx] = h;
        tl[kk][tx] = __float2bfloat16_rn(x - __bfloat162float(h));
    }
    __syncthreads();
    #pragma unroll
    for (int i = 0; i < 4; i++) {
        const int nn = ty + i * 8;
        g_Wthi[(size_t)(n0 + nn) * F_IN + k0 + tx] = th[tx][nn];
        g_Wtlo[(size_t)(n0 + nn) * F_IN + k0 + tx] = tl[tx][nn];
    }
}

// =====================================================================
// Kernel C: bf16x3 tensor-core GEMM, 3-stage cp.async, 8 warps 64x64,
// EXPLICIT fragment software pipeline: LDSM for step s+1 issued before
// the mma burst of step s, so crossbar and tensor pipe overlap.
// =====================================================================
#define GM 128
#define GN 256
#define GK 32
#define NCH (F_IN / GK)          // 128
#define ROWB 80                  // 32 bf16 + 8 pad bytes
#define SA_HI 0
#define SA_LO (GM * ROWB)
#define SB_HI (2 * GM * ROWB)
#define STAGE (2 * GM * ROWB + 2 * GN * ROWB)  // 61440
#define NSTAGE 3
#define GEMM_SMEM (NSTAGE * STAGE)             // 184320

__device__ __forceinline__ void copy_chunk(uint32_t sb, int blockRow, int blockCol,
                                           int c, int tid)
{
    const size_t kc = (size_t)c * GK;
    #pragma unroll
    for (int i = 0; i < 4; i++) {
        const int id  = tid + i * 256;
        const int arr = id >> 9;
        const int rid = (id >> 2) & 127;
        const int seg = id & 3;
        const char* src = (const char*)(arr ? g_Alo : g_Ahi)
                        + ((size_t)(blockRow + rid) * F_IN + kc) * 2 + seg * 16;
        cp_async16(sb + arr * (GM * ROWB) + rid * ROWB + seg * 16, src);
    }
    #pragma unroll
    for (int i = 0; i < 8; i++) {
        const int id  = tid + i * 256;
        const int arr = id >> 10;
        const int rid = (id >> 2) & 255;
        const int seg = id & 3;
        const char* src = (const char*)(arr ? g_Wtlo : g_Wthi)
                        + ((size_t)(blockCol + rid) * F_IN + kc) * 2 + seg * 16;
        cp_async16(sb + SB_HI + arr * (GN * ROWB) + rid * ROWB + seg * 16, src);
    }
}

// one full pass over the 64x64 warp tile: 32 HMMA
#define MMA_PASS(ACC, A, B)                                   \
    _Pragma("unroll")                                         \
    for (int mt = 0; mt < 4; mt++) {                          \
        _Pragma("unroll")                                     \
        for (int p = 0; p < 4; p++) {                         \
            mma_bf16(ACC[mt][p * 2 + 0], A[mt], &B[p][0]);    \
            mma_bf16(ACC[mt][p * 2 + 1], A[mt], &B[p][2]);    \
        }                                                     \
    }

#define LOAD_A(F, st, base, kb)                                           \
    _Pragma("unroll")                                                     \
    for (int mt = 0; mt < 4; mt++)                                        \
        ldmx4(F[mt], (st) + aOff + (base) + mt * (16 * ROWB) + (kb));

#define LOAD_B(F, st, arrOff, kb)                                         \
    _Pragma("unroll")                                                     \
    for (int p = 0; p < 4; p++)                                           \
        ldmx4(F[p], (st) + bOff[p] + (arrOff) + (kb));

__global__ __launch_bounds__(256)
void gemm_bf16x3(const float* __restrict__ bias)
{
    extern __shared__ char smem[];
    const uint32_t sbase = smem_u32(smem);
    const int tid = threadIdx.x;
    const int wid = tid >> 5;
    const int l   = tid & 31;
    const int warpM = wid >> 2;          // 0..1 -> 64-row strip
    const int warpN = wid & 3;           // 0..3 -> 64-col strip
    const int blockRow = blockIdx.y * GM;
    const int blockCol = blockIdx.x * GN;

    const uint32_t aOff = (uint32_t)((warpM * 64 + (l & 15)) * ROWB + (l >> 4) * 16);
    uint32_t bOff[4];
    #pragma unroll
    for (int p = 0; p < 4; p++)
        bOff[p] = (uint32_t)(SB_HI + (warpN * 64 + p * 16 + ((l >> 4) & 1) * 8 + (l & 7)) * ROWB
                             + ((l >> 3) & 1) * 16);

    float acc[4][8][4];
    #pragma unroll
    for (int mt = 0; mt < 4; mt++)
        #pragma unroll
        for (int nt = 0; nt < 8; nt++)
            #pragma unroll
            for (int r = 0; r < 4; r++) acc[mt][nt][r] = 0.f;

    copy_chunk(sbase, blockRow, blockCol, 0, tid);
    cp_commit();
    copy_chunk(sbase + STAGE, blockRow, blockCol, 1, tid);
    cp_commit();

    uint32_t stOff = 0;
    uint32_t wrOff = 2 * STAGE;

    for (int c = 0; c < NCH; c++) {
        cp_wait1();
        __syncthreads();

        if (c + 2 < NCH) copy_chunk(sbase + wrOff, blockRow, blockCol, c + 2, tid);
        cp_commit();

        const uint32_t st = sbase + stOff;
        uint32_t aH[4][4], aH2[4][4], aL[4][4], bH[4][4], bH2[4][4], bL[4][4];

        // ---- fragment pipeline: load(s+1) before mma(s) ----
        LOAD_A(aH, st, SA_HI, 0);             // hh0 operands
        LOAD_B(bH, st, 0, 0);

        LOAD_A(aL, st, SA_LO, 0);             // prefetch lh0
        MMA_PASS(acc, aH, bH);                // hh0

        LOAD_B(bL, st, GN * ROWB, 0);         // prefetch hl0
        MMA_PASS(acc, aL, bH);                // lh0

        LOAD_A(aH2, st, SA_HI, 32);           // prefetch hh1
        LOAD_B(bH2, st, 0, 32);
        MMA_PASS(acc, aH, bL);                // hl0

        LOAD_A(aL, st, SA_LO, 32);            // prefetch lh1 (aL dead)
        MMA_PASS(acc, aH2, bH2);              // hh1

        LOAD_B(bL, st, GN * ROWB, 32);        // prefetch hl1 (bL dead)
        MMA_PASS(acc, aL, bH2);               // lh1

        MMA_PASS(acc, aH2, bL);               // hl1

        stOff += STAGE; if (stOff == NSTAGE * STAGE) stOff = 0;
        wrOff += STAGE; if (wrOff == NSTAGE * STAGE) wrOff = 0;
    }

    // epilogue: + bias, store fp32
    #pragma unroll
    for (int mt = 0; mt < 4; mt++) {
        const int r0 = blockRow + warpM * 64 + mt * 16 + (l >> 2);
        #pragma unroll
        for (int nt = 0; nt < 8; nt++) {
            const int col = blockCol + warpN * 64 + nt * 8 + (l & 3) * 2;
            const float b0 = bias[col], b1 = bias[col + 1];
            float2 v0 = make_float2(acc[mt][nt][0] + b0, acc[mt][nt][1] + b1);
            float2 v1 = make_float2(acc[mt][nt][2] + b0, acc[mt][nt][3] + b1);
            *(float2*)(g_Z + (size_t)r0 * D_EMB + col)       = v0;
            *(float2*)(g_Z + (size_t)(r0 + 8) * D_EMB + col) = v1;
        }
    }
}

// =====================================================================
// Kernel E: prototypes (lower median + mean) with inline stable order
// scan (warp 0 ballot compaction), class stats. One block per class.
// =====================================================================
__global__ __launch_bounds__(256)
void proto_kernel(const int* __restrict__ labels)
{
    const int c   = blockIdx.x;
    const int tid = threadIdx.x;
    const int l   = tid & 31;
    __shared__ float s_sum[256], s_sum2[256];
    __shared__ int   s_idx[K_SHOT];

    if (c < N_WAY && tid < 32) {
        int base = 0;
        for (int i0 = 0; i0 < N_SUPPORT; i0 += 32) {
            const int i = i0 + l;
            const bool match = (i < N_SUPPORT) && (labels[i] == c);
            const unsigned m = __ballot_sync(0xFFFFFFFFu, match);
            if (match) {
                const int pos = base + __popc(m & ((1u << l) - 1u));
                if (pos < K_SHOT) s_idx[pos] = i;
            }
            base += __popc(m);
        }
    }
    __syncthreads();

    float psum = 0.f, psum2 = 0.f;
    if (c < N_WAY) {
        int idx[K_SHOT];
        #pragma unroll
        for (int j = 0; j < K_SHOT; j++) idx[j] = s_idx[j];

        for (int d = tid; d < D_EMB; d += 256) {
            float v[K_SHOT];
            #pragma unroll
            for (int j = 0; j < K_SHOT; j++)
                v[j] = g_Z[(size_t)(N_QUERY + idx[j]) * D_EMB + d];

            float mean = 0.f;
            #pragma unroll
            for (int j = 0; j < K_SHOT; j++) mean += v[j];
            mean *= (1.0f / K_SHOT);

            #pragma unroll
            for (int p = 0; p < K_SHOT - 1; p++)
                #pragma unroll
                for (int q = 0; q < K_SHOT - 1 - p; q++) {
                    float lo = fminf(v[q], v[q + 1]);
                    float hi = fmaxf(v[q], v[q + 1]);
                    v[q] = lo; v[q + 1] = hi;
                }
            const float med = v[(K_SHOT - 1) / 2];
            const float zt  = 0.5f * (med + mean);
            g_proto[(size_t)c * D_EMB + d] = zt;
            psum += zt; psum2 += zt * zt;
        }
    } else {
        for (int d = tid; d < D_EMB; d += 256)
            g_proto[(size_t)c * D_EMB + d] = 0.f;
    }

    s_sum[tid] = psum; s_sum2[tid] = psum2;
    __syncthreads();
    for (int s = 128; s > 0; s >>= 1) {
        if (tid < s) { s_sum[tid] += s_sum[tid + s]; s_sum2[tid] += s_sum2[tid + s]; }
        __syncthreads();
    }
    if (tid == 0 && c < N_WAY) { g_ps[c] = s_sum[0]; g_p2[c] = s_sum2[0]; }
}

// =====================================================================
// Kernel F: per-query-row sum / sum-of-squares — warp per row (fp32)
// =====================================================================
__global__ __launch_bounds__(256)
void qstats_kernel()
{
    const int warp = (blockIdx.x * blockDim.x + threadIdx.x) >> 5;
    const int l    = threadIdx.x & 31;
    if (warp >= N_QUERY) return;
    const float* z = g_Z + (size_t)warp * D_EMB;
    float s = 0.f, s2 = 0.f;
    #pragma unroll
    for (int i = 0; i < 8; i++) {
        float4 v = *(const float4*)(z + (l + i * 32) * 4);
        s  += v.x + v.y + v.z + v.w;
        s2 += v.x * v.x + v.y * v.y + v.z * v.z + v.w * v.w;
    }
    #pragma unroll
    for (int off = 16; off > 0; off >>= 1) {
        s  += __shfl_xor_sync(0xFFFFFFFFu, s,  off);
        s2 += __shfl_xor_sync(0xFFFFFFFFu, s2, off);
    }
    if (l == 0) { g_qs[warp] = s; g_q2[warp] = s2; }
}

// =====================================================================
// Kernel G: distance matrix (SIMT) with fused PairwiseDistance-eps
// =====================================================================
#define DBM 64
#define DBN 128
#define DBK 16
#define DTM 4
#define DTN 8

__global__ __launch_bounds__(256)
void dist_kernel(float* __restrict__ out)
{
    __shared__ float As2[DBK][DBM];
    __shared__ float Bs2[DBK][DBN];

    const int tid      = threadIdx.x;
    const int blockRow = blockIdx.x * DBM;

    const int aRow = tid >> 2;
    const int aCol = (tid & 3) << 2;
    const int tr = (tid >> 4) * DTM;
    const int tc = (tid & 15) * DTN;

    float acc[DTM][DTN] = {};

    const int nk = D_EMB / DBK;
    for (int kt = 0; kt < nk; kt++) {
        const int kc = kt * DBK;
        {
            float4 a = *(const float4*)(g_Z + (size_t)(blockRow + aRow) * D_EMB + kc + aCol);
            As2[aCol + 0][aRow] = a.x; As2[aCol + 1][aRow] = a.y;
            As2[aCol + 2][aRow] = a.z; As2[aCol + 3][aRow] = a.w;
        }
        #pragma unroll
        for (int s = 0; s < 2; s++) {
            const int idx = tid + s * 256;
            const int n   = idx >> 2;
            const int k4  = (idx & 3) << 2;
            float4 p = *(const float4*)(g_proto + (size_t)n * D_EMB + kc + k4);
            Bs2[k4 + 0][n] = p.x; Bs2[k4 + 1][n] = p.y;
            Bs2[k4 + 2][n] = p.z; Bs2[k4 + 3][n] = p.w;
        }
        __syncthreads();

        #pragma unroll
        for (int k = 0; k < DBK; k++) {
            float ar[DTM], br[DTN];
            *(float4*)&ar[0] = *(const float4*)&As2[k][tr];
            *(float4*)&br[0] = *(const float4*)&Bs2[k][tc];
            *(float4*)&br[4] = *(const float4*)&Bs2[k][tc + 4];
            #pragma unroll
            for (int i = 0; i < DTM; i++)
                #pragma unroll
                for (int j = 0; j < DTN; j++)
                    acc[i][j] += ar[i] * br[j];
        }
        __syncthreads();
    }

    const float deps2 = (float)D_EMB * EPS_F * EPS_F;
    #pragma unroll
    for (int i = 0; i < DTM; i++) {
        const int r = blockRow + tr + i;
        const float q2v = g_q2[r];
        const float qsv = g_qs[r];
        #pragma unroll
        for (int j = 0; j < DTN; j++) {
            const int c = tc + j;
            if (c < N_WAY) {
                float sq = q2v + g_p2[c] - 2.0f * acc[i][j]
                         + 2.0f * EPS_F * (qsv - g_ps[c]) + deps2;
                out[(size_t)r * N_WAY + c] = -sqrtf(fmaxf(sq, 0.0f));
            }
        }
    }
}

// =====================================================================
// launch
// =====================================================================
extern "C" void kernel_launch(void* const* d_in, const int* in_sizes, int n_in,
                              void* d_out, int out_size)
{
    const float* support = (const float*)d_in[0];
    const int*   labels  = (const int*)  d_in[1];
    const float* query   = (const float*)d_in[2];
    const float* W       = (const float*)d_in[3];
    const float* b       = (const float*)d_in[4];
    float*       out     = (float*)d_out;

    cudaFuncSetAttribute(gemm_bf16x3,
                         cudaFuncAttributeMaxDynamicSharedMemorySize, GEMM_SMEM);

    {
        const size_t total = (size_t)M_TOT * F_IN / 4;
        convert_A<<<(unsigned)((total + 255) / 256), 256>>>(query, support);
    }
    convert_W<<<dim3(F_IN / 32, D_EMB / 32), dim3(32, 8)>>>(W);

    gemm_bf16x3<<<dim3(D_EMB / GN, M_TOT / GM), 256, GEMM_SMEM>>>(b);

    proto_kernel<<<128, 256>>>(labels);
    qstats_kernel<<<N_QUERY / 8, 256>>>();
    dist_kernel<<<N_QUERY / DBM, 256>>>(out);
}

// round 8
// speedup vs baseline: 1.0226x; 1.0226x over previous
#include <cuda_runtime.h>
#include <cuda_bf16.h>
#include <math.h>
#include <stdint.h>

#define N_WAY     100
#define K_SHOT    10
#define N_SUPPORT 1000
#define N_QUERY   8192
#define F_IN      4096
#define D_EMB     1024
#define EPS_F     1e-6f

#define M_TOT     9216   // 8192 query rows + 1000 support + 24 pad

// ---------------- scratch (static device globals; no allocations) ----------
__device__ __nv_bfloat16 g_Ahi[(size_t)M_TOT * F_IN];
__device__ __nv_bfloat16 g_Alo[(size_t)M_TOT * F_IN];
__device__ __nv_bfloat16 g_Wthi[(size_t)D_EMB * F_IN];
__device__ __nv_bfloat16 g_Wtlo[(size_t)D_EMB * F_IN];
__device__ float g_Z[(size_t)M_TOT * D_EMB];
__device__ float g_proto[128 * D_EMB];
__device__ float g_p2[128];
__device__ float g_ps[128];
__device__ float g_q2[N_QUERY];
__device__ float g_qs[N_QUERY];

// ======================= portable PTX helpers ==============================
__device__ __forceinline__ uint32_t smem_u32(const void* p) {
    uint32_t a;
    asm("{ .reg .u64 t; cvta.to.shared.u64 t, %1; cvt.u32.u64 %0, t; }"
        : "=r"(a) : "l"(p));
    return a;
}
__device__ __forceinline__ void cp_async16(uint32_t dst, const void* src) {
    asm volatile("cp.async.cg.shared.global [%0], [%1], 16;"
                 :: "r"(dst), "l"(src) : "memory");
}
__device__ __forceinline__ void cp_commit() {
    asm volatile("cp.async.commit_group;" ::: "memory");
}
__device__ __forceinline__ void cp_wait1() {
    asm volatile("cp.async.wait_group 1;" ::: "memory");
}
__device__ __forceinline__ void ldmx4(uint32_t* r, uint32_t addr) {
    asm volatile("ldmatrix.sync.aligned.m8n8.x4.shared.b16 {%0,%1,%2,%3}, [%4];"
                 : "=r"(r[0]), "=r"(r[1]), "=r"(r[2]), "=r"(r[3]) : "r"(addr));
}
__device__ __forceinline__ void mma_bf16(float* c, const uint32_t* a, const uint32_t* b) {
    asm volatile(
        "mma.sync.aligned.m16n8k16.row.col.f32.bf16.bf16.f32 "
        "{%0,%1,%2,%3}, {%4,%5,%6,%7}, {%8,%9}, {%0,%1,%2,%3};"
        : "+f"(c[0]), "+f"(c[1]), "+f"(c[2]), "+f"(c[3])
        : "r"(a[0]), "r"(a[1]), "r"(a[2]), "r"(a[3]), "r"(b[0]), "r"(b[1]));
}

// =====================================================================
// Kernel A: split fp32 inputs into bf16 hi/lo
// =====================================================================
__global__ void convert_A(const float* __restrict__ q, const float* __restrict__ s)
{
    size_t i = (size_t)blockIdx.x * blockDim.x + threadIdx.x;
    const size_t total = (size_t)M_TOT * F_IN / 4;
    if (i >= total) return;
    const size_t row = i / (F_IN / 4);
    const size_t seg = i % (F_IN / 4);
    float4 v;
    if (row < N_QUERY)                  v = *(const float4*)(q + row * F_IN + seg * 4);
    else if (row < N_QUERY + N_SUPPORT) v = *(const float4*)(s + (row - N_QUERY) * F_IN + seg * 4);
    else                                v = make_float4(0.f, 0.f, 0.f, 0.f);

    float x[4] = {v.x, v.y, v.z, v.w};
    union B4 { __nv_bfloat16 b[4]; uint2 u; } uh, ul;
    #pragma unroll
    for (int j = 0; j < 4; j++) {
        __nv_bfloat16 h = __float2bfloat16_rn(x[j]);
        uh.b[j] = h;
        ul.b[j] = __float2bfloat16_rn(x[j] - __bfloat162float(h));
    }
    *(uint2*)(g_Ahi + i * 4) = uh.u;
    *(uint2*)(g_Alo + i * 4) = ul.u;
}

// =====================================================================
// Kernel B: transpose W [4096,1024] -> Wt hi/lo [1024,4096] bf16
// =====================================================================
__global__ void convert_W(const float* __restrict__ W)
{
    __shared__ __nv_bfloat16 th[32][33];
    __shared__ __nv_bfloat16 tl[32][33];
    const int k0 = blockIdx.x * 32, n0 = blockIdx.y * 32;
    const int tx = threadIdx.x, ty = threadIdx.y;   // (32, 8)
    #pragma unroll
    for (int i = 0; i < 4; i++) {
        const int kk = ty + i * 8;
        float x = W[(size_t)(k0 + kk) * D_EMB + n0 + tx];
        __nv_bfloat16 h = __float2bfloat16_rn(x);
        th[kk][tx] = h;
        tl[kk][tx] = __float2bfloat16_rn(x - __bfloat162float(h));
    }
    __syncthreads();
    #pragma unroll
    for (int i = 0; i < 4; i++) {
        const int nn = ty + i * 8;
        g_Wthi[(size_t)(n0 + nn) * F_IN + k0 + tx] = th[tx][nn];
        g_Wtlo[(size_t)(n0 + nn) * F_IN + k0 + tx] = tl[tx][nn];
    }
}

// =====================================================================
// Kernel C: bf16x3 tensor-core GEMM. 128x128 tile, 8 warps (32x64 warp
// tile), 2-stage cp.async, TWO CTAs PER SM so the per-chunk barrier
// bubbles of one CTA are filled by the other CTA's mma stream.
// =====================================================================
#define GM 128
#define GN 128
#define GK 32
#define NCH (F_IN / GK)          // 128
#define ROWB 80                  // 32 bf16 + 8 pad bytes
#define SA_HI 0
#define SA_LO (GM * ROWB)                    // 10240
#define SB_HI (2 * GM * ROWB)                // 20480
#define STAGE (2 * GM * ROWB + 2 * GN * ROWB)  // 40960
#define NSTAGE 2
#define GEMM_SMEM (NSTAGE * STAGE)             // 81920

__device__ __forceinline__ void copy_chunk(uint32_t sb, int blockRow, int blockCol,
                                           int c, int tid)
{
    const size_t kc = (size_t)c * GK;
    // A hi+lo: 128 rows x 4 segs x 2 = 1024 x 16B, 256 thr -> 4 iters
    #pragma unroll
    for (int i = 0; i < 4; i++) {
        const int id  = tid + i * 256;
        const int arr = id >> 9;
        const int rid = (id >> 2) & 127;
        const int seg = id & 3;
        const char* src = (const char*)(arr ? g_Alo : g_Ahi)
                        + ((size_t)(blockRow + rid) * F_IN + kc) * 2 + seg * 16;
        cp_async16(sb + arr * (GM * ROWB) + rid * ROWB + seg * 16, src);
    }
    // B hi+lo: 128 rows x 4 segs x 2 = 1024 x 16B
    #pragma unroll
    for (int i = 0; i < 4; i++) {
        const int id  = tid + i * 256;
        const int arr = id >> 9;
        const int rid = (id >> 2) & 127;
        const int seg = id & 3;
        const char* src = (const char*)(arr ? g_Wtlo : g_Wthi)
                        + ((size_t)(blockCol + rid) * F_IN + kc) * 2 + seg * 16;
        cp_async16(sb + SB_HI + arr * (GN * ROWB) + rid * ROWB + seg * 16, src);
    }
}

__global__ __launch_bounds__(256, 2)
void gemm_bf16x3(const float* __restrict__ bias)
{
    extern __shared__ char smem[];
    const uint32_t sbase = smem_u32(smem);
    const int tid = threadIdx.x;
    const int wid = tid >> 5;
    const int l   = tid & 31;
    const int warpM = wid & 3;           // 4 strips of 32 rows
    const int warpN = wid >> 2;          // 2 strips of 64 cols
    const int blockRow = blockIdx.y * GM;
    const int blockCol = blockIdx.x * GN;

    const uint32_t aOff = (uint32_t)((warpM * 32 + (l & 15)) * ROWB + (l >> 4) * 16);
    uint32_t bOff[4];
    #pragma unroll
    for (int p = 0; p < 4; p++)
        bOff[p] = (uint32_t)(SB_HI + (warpN * 64 + p * 16 + ((l >> 4) & 1) * 8 + (l & 7)) * ROWB
                             + ((l >> 3) & 1) * 16);

    float acc[2][8][4];
    #pragma unroll
    for (int mt = 0; mt < 2; mt++)
        #pragma unroll
        for (int nt = 0; nt < 8; nt++)
            #pragma unroll
            for (int r = 0; r < 4; r++) acc[mt][nt][r] = 0.f;

    // prologue: chunk 0 -> stage 0
    copy_chunk(sbase, blockRow, blockCol, 0, tid);
    cp_commit();

    for (int c = 0; c < NCH; c++) {
        const uint32_t cur = (uint32_t)(c & 1);
        // issue chunk c+1 into the other stage (freed by the end-of-iter
        // barrier of chunk c-1)
        if (c + 1 < NCH) copy_chunk(sbase + (cur ^ 1) * STAGE, blockRow, blockCol, c + 1, tid);
        cp_commit();
        cp_wait1();                       // chunk c resident
        __syncthreads();

        const uint32_t st = sbase + cur * STAGE;
        #pragma unroll
        for (int ks = 0; ks < 2; ks++) {
            const uint32_t kb = ks * 32;
            uint32_t aH[2][4], aL[2][4], bH[4][4], bL[4][4];

            #pragma unroll
            for (int mt = 0; mt < 2; mt++) ldmx4(aH[mt], st + aOff + mt * (16 * ROWB) + kb);
            #pragma unroll
            for (int p = 0; p < 4; p++)   ldmx4(bH[p], st + bOff[p] + kb);

            // pass 1: hi * hi
            #pragma unroll
            for (int mt = 0; mt < 2; mt++)
                #pragma unroll
                for (int p = 0; p < 4; p++) {
                    mma_bf16(acc[mt][p * 2 + 0], aH[mt], &bH[p][0]);
                    mma_bf16(acc[mt][p * 2 + 1], aH[mt], &bH[p][2]);
                }

            // pass 2: lo * hi
            #pragma unroll
            for (int mt = 0; mt < 2; mt++) ldmx4(aL[mt], st + aOff + SA_LO + mt * (16 * ROWB) + kb);
            #pragma unroll
            for (int mt = 0; mt < 2; mt++)
                #pragma unroll
                for (int p = 0; p < 4; p++) {
                    mma_bf16(acc[mt][p * 2 + 0], aL[mt], &bH[p][0]);
                    mma_bf16(acc[mt][p * 2 + 1], aL[mt], &bH[p][2]);
                }

            // pass 3: hi * lo
            #pragma unroll
            for (int p = 0; p < 4; p++)   ldmx4(bL[p], st + bOff[p] + (GN * ROWB) + kb);
            #pragma unroll
            for (int mt = 0; mt < 2; mt++)
                #pragma unroll
                for (int p = 0; p < 4; p++) {
                    mma_bf16(acc[mt][p * 2 + 0], aH[mt], &bL[p][0]);
                    mma_bf16(acc[mt][p * 2 + 1], aH[mt], &bL[p][2]);
                }
        }
        __syncthreads();   // all warps done reading stage cur before it is overwritten
    }

    // epilogue: + bias, store fp32
    #pragma unroll
    for (int mt = 0; mt < 2; mt++) {
        const int r0 = blockRow + warpM * 32 + mt * 16 + (l >> 2);
        #pragma unroll
        for (int nt = 0; nt < 8; nt++) {
            const int col = blockCol + warpN * 64 + nt * 8 + (l & 3) * 2;
            const float b0 = bias[col], b1 = bias[col + 1];
            float2 v0 = make_float2(acc[mt][nt][0] + b0, acc[mt][nt][1] + b1);
            float2 v1 = make_float2(acc[mt][nt][2] + b0, acc[mt][nt][3] + b1);
            *(float2*)(g_Z + (size_t)r0 * D_EMB + col)       = v0;
            *(float2*)(g_Z + (size_t)(r0 + 8) * D_EMB + col) = v1;
        }
    }
}

// =====================================================================
// Kernel E: prototypes (lower median + mean) with inline stable order
// scan (warp 0 ballot compaction), class stats. One block per class.
// =====================================================================
__global__ __launch_bounds__(256)
void proto_kernel(const int* __restrict__ labels)
{
    const int c   = blockIdx.x;
    const int tid = threadIdx.x;
    const int l   = tid & 31;
    __shared__ float s_sum[256], s_sum2[256];
    __shared__ int   s_idx[K_SHOT];

    if (c < N_WAY && tid < 32) {
        int base = 0;
        for (int i0 = 0; i0 < N_SUPPORT; i0 += 32) {
            const int i = i0 + l;
            const bool match = (i < N_SUPPORT) && (labels[i] == c);
            const unsigned m = __ballot_sync(0xFFFFFFFFu, match);
            if (match) {
                const int pos = base + __popc(m & ((1u << l) - 1u));
                if (pos < K_SHOT) s_idx[pos] = i;
            }
            base += __popc(m);
        }
    }
    __syncthreads();

    float psum = 0.f, psum2 = 0.f;
    if (c < N_WAY) {
        int idx[K_SHOT];
        #pragma unroll
        for (int j = 0; j < K_SHOT; j++) idx[j] = s_idx[j];

        for (int d = tid; d < D_EMB; d += 256) {
            float v[K_SHOT];
            #pragma unroll
            for (int j = 0; j < K_SHOT; j++)
                v[j] = g_Z[(size_t)(N_QUERY + idx[j]) * D_EMB + d];

            float mean = 0.f;
            #pragma unroll
            for (int j = 0; j < K_SHOT; j++) mean += v[j];
            mean *= (1.0f / K_SHOT);

            #pragma unroll
            for (int p = 0; p < K_SHOT - 1; p++)
                #pragma unroll
                for (int q = 0; q < K_SHOT - 1 - p; q++) {
                    float lo = fminf(v[q], v[q + 1]);
                    float hi = fmaxf(v[q], v[q + 1]);
                    v[q] = lo; v[q + 1] = hi;
                }
            const float med = v[(K_SHOT - 1) / 2];
            const float zt  = 0.5f * (med + mean);
            g_proto[(size_t)c * D_EMB + d] = zt;
            psum += zt; psum2 += zt * zt;
        }
    } else {
        for (int d = tid; d < D_EMB; d += 256)
            g_proto[(size_t)c * D_EMB + d] = 0.f;
    }

    s_sum[tid] = psum; s_sum2[tid] = psum2;
    __syncthreads();
    for (int s = 128; s > 0; s >>= 1) {
        if (tid < s) { s_sum[tid] += s_sum[tid + s]; s_sum2[tid] += s_sum2[tid + s]; }
        __syncthreads();
    }
    if (tid == 0 && c < N_WAY) { g_ps[c] = s_sum[0]; g_p2[c] = s_sum2[0]; }
}

// =====================================================================
// Kernel F: per-query-row sum / sum-of-squares — warp per row (fp32)
// =====================================================================
__global__ __launch_bounds__(256)
void qstats_kernel()
{
    const int warp = (blockIdx.x * blockDim.x + threadIdx.x) >> 5;
    const int l    = threadIdx.x & 31;
    if (warp >= N_QUERY) return;
    const float* z = g_Z + (size_t)warp * D_EMB;
    float s = 0.f, s2 = 0.f;
    #pragma unroll
    for (int i = 0; i < 8; i++) {
        float4 v = *(const float4*)(z + (l + i * 32) * 4);
        s  += v.x + v.y + v.z + v.w;
        s2 += v.x * v.x + v.y * v.y + v.z * v.z + v.w * v.w;
    }
    #pragma unroll
    for (int off = 16; off > 0; off >>= 1) {
        s  += __shfl_xor_sync(0xFFFFFFFFu, s,  off);
        s2 += __shfl_xor_sync(0xFFFFFFFFu, s2, off);
    }
    if (l == 0) { g_qs[warp] = s; g_q2[warp] = s2; }
}

// =====================================================================
// Kernel G: distance matrix (SIMT) with fused PairwiseDistance-eps
// =====================================================================
#define DBM 64
#define DBN 128
#define DBK 16
#define DTM 4
#define DTN 8

__global__ __launch_bounds__(256)
void dist_kernel(float* __restrict__ out)
{
    __shared__ float As2[DBK][DBM];
    __shared__ float Bs2[DBK][DBN];

    const int tid      = threadIdx.x;
    const int blockRow = blockIdx.x * DBM;

    const int aRow = tid >> 2;
    const int aCol = (tid & 3) << 2;
    const int tr = (tid >> 4) * DTM;
    const int tc = (tid & 15) * DTN;

    float acc[DTM][DTN] = {};

    const int nk = D_EMB / DBK;
    for (int kt = 0; kt < nk; kt++) {
        const int kc = kt * DBK;
        {
            float4 a = *(const float4*)(g_Z + (size_t)(blockRow + aRow) * D_EMB + kc + aCol);
            As2[aCol + 0][aRow] = a.x; As2[aCol + 1][aRow] = a.y;
            As2[aCol + 2][aRow] = a.z; As2[aCol + 3][aRow] = a.w;
        }
        #pragma unroll
        for (int s = 0; s < 2; s++) {
            const int idx = tid + s * 256;
            const int n   = idx >> 2;
            const int k4  = (idx & 3) << 2;
            float4 p = *(const float4*)(g_proto + (size_t)n * D_EMB + kc + k4);
            Bs2[k4 + 0][n] = p.x; Bs2[k4 + 1][n] = p.y;
            Bs2[k4 + 2][n] = p.z; Bs2[k4 + 3][n] = p.w;
        }
        __syncthreads();

        #pragma unroll
        for (int k = 0; k < DBK; k++) {
            float ar[DTM], br[DTN];
            *(float4*)&ar[0] = *(const float4*)&As2[k][tr];
            *(float4*)&br[0] = *(const float4*)&Bs2[k][tc];
            *(float4*)&br[4] = *(const float4*)&Bs2[k][tc + 4];
            #pragma unroll
            for (int i = 0; i < DTM; i++)
                #pragma unroll
                for (int j = 0; j < DTN; j++)
                    acc[i][j] += ar[i] * br[j];
        }
        __syncthreads();
    }

    const float deps2 = (float)D_EMB * EPS_F * EPS_F;
    #pragma unroll
    for (int i = 0; i < DTM; i++) {
        const int r = blockRow + tr + i;
        const float q2v = g_q2[r];
        const float qsv = g_qs[r];
        #pragma unroll
        for (int j = 0; j < DTN; j++) {
            const int c = tc + j;
            if (c < N_WAY) {
                float sq = q2v + g_p2[c] - 2.0f * acc[i][j]
                         + 2.0f * EPS_F * (qsv - g_ps[c]) + deps2;
                out[(size_t)r * N_WAY + c] = -sqrtf(fmaxf(sq, 0.0f));
            }
        }
    }
}

// =====================================================================
// launch
// =====================================================================
extern "C" void kernel_launch(void* const* d_in, const int* in_sizes, int n_in,
                              void* d_out, int out_size)
{
    const float* support = (const float*)d_in[0];
    const int*   labels  = (const int*)  d_in[1];
    const float* query   = (const float*)d_in[2];
    const float* W       = (const float*)d_in[3];
    const float* b       = (const float*)d_in[4];
    float*       out     = (float*)d_out;

    cudaFuncSetAttribute(gemm_bf16x3,
                         cudaFuncAttributeMaxDynamicSharedMemorySize, GEMM_SMEM);

    {
        const size_t total = (size_t)M_TOT * F_IN / 4;
        convert_A<<<(unsigned)((total + 255) / 256), 256>>>(query, support);
    }
    convert_W<<<dim3(F_IN / 32, D_EMB / 32), dim3(32, 8)>>>(W);

    gemm_bf16x3<<<dim3(D_EMB / GN, M_TOT / GM), 256, GEMM_SMEM>>>(b);

    proto_kernel<<<128, 256>>>(labels);
    qstats_kernel<<<N_QUERY / 8, 256>>>();
    dist_kernel<<<N_QUERY / DBM, 256>>>(out);
}

// round 9
// speedup vs baseline: 1.1041x; 1.0797x over previous
#include <cuda_runtime.h>
#include <cuda_bf16.h>
#include <math.h>
#include <stdint.h>

#define N_WAY     100
#define K_SHOT    10
#define N_SUPPORT 1000
#define N_QUERY   8192
#define F_IN      4096
#define D_EMB     1024
#define EPS_F     1e-6f

#define M_TOT     9216   // 8192 query rows + 1000 support + 24 pad

// ---------------- scratch (static device globals; no allocations) ----------
__device__ __nv_bfloat16 g_Ahi[(size_t)M_TOT * F_IN];
__device__ __nv_bfloat16 g_Alo[(size_t)M_TOT * F_IN];
__device__ __nv_bfloat16 g_Wthi[(size_t)D_EMB * F_IN];
__device__ __nv_bfloat16 g_Wtlo[(size_t)D_EMB * F_IN];
__device__ float g_Z[(size_t)M_TOT * D_EMB];
__device__ float g_proto[128 * D_EMB];
__device__ float g_p2[128];
__device__ float g_ps[128];
__device__ float g_q2[N_QUERY];
__device__ float g_qs[N_QUERY];

// ======================= portable PTX helpers ==============================
__device__ __forceinline__ uint32_t smem_u32(const void* p) {
    uint32_t a;
    asm("{ .reg .u64 t; cvta.to.shared.u64 t, %1; cvt.u32.u64 %0, t; }"
        : "=r"(a) : "l"(p));
    return a;
}
__device__ __forceinline__ void cp_async16(uint32_t dst, const void* src) {
    asm volatile("cp.async.cg.shared.global [%0], [%1], 16;"
                 :: "r"(dst), "l"(src) : "memory");
}
__device__ __forceinline__ void cp_commit() {
    asm volatile("cp.async.commit_group;" ::: "memory");
}
__device__ __forceinline__ void cp_wait0() {
    asm volatile("cp.async.wait_group 0;" ::: "memory");
}
__device__ __forceinline__ void ldmx4(uint32_t* r, uint32_t addr) {
    asm volatile("ldmatrix.sync.aligned.m8n8.x4.shared.b16 {%0,%1,%2,%3}, [%4];"
                 : "=r"(r[0]), "=r"(r[1]), "=r"(r[2]), "=r"(r[3]) : "r"(addr));
}
__device__ __forceinline__ void mma_bf16(float* c, const uint32_t* a, const uint32_t* b) {
    asm volatile(
        "mma.sync.aligned.m16n8k16.row.col.f32.bf16.bf16.f32 "
        "{%0,%1,%2,%3}, {%4,%5,%6,%7}, {%8,%9}, {%0,%1,%2,%3};"
        : "+f"(c[0]), "+f"(c[1]), "+f"(c[2]), "+f"(c[3])
        : "r"(a[0]), "r"(a[1]), "r"(a[2]), "r"(a[3]), "r"(b[0]), "r"(b[1]));
}

// =====================================================================
// Kernel A: split fp32 inputs into bf16 hi/lo
// =====================================================================
__global__ void convert_A(const float* __restrict__ q, const float* __restrict__ s)
{
    size_t i = (size_t)blockIdx.x * blockDim.x + threadIdx.x;
    const size_t total = (size_t)M_TOT * F_IN / 4;
    if (i >= total) return;
    const size_t row = i / (F_IN / 4);
    const size_t seg = i % (F_IN / 4);
    float4 v;
    if (row < N_QUERY)                  v = *(const float4*)(q + row * F_IN + seg * 4);
    else if (row < N_QUERY + N_SUPPORT) v = *(const float4*)(s + (row - N_QUERY) * F_IN + seg * 4);
    else                                v = make_float4(0.f, 0.f, 0.f, 0.f);

    float x[4] = {v.x, v.y, v.z, v.w};
    union B4 { __nv_bfloat16 b[4]; uint2 u; } uh, ul;
    #pragma unroll
    for (int j = 0; j < 4; j++) {
        __nv_bfloat16 h = __float2bfloat16_rn(x[j]);
        uh.b[j] = h;
        ul.b[j] = __float2bfloat16_rn(x[j] - __bfloat162float(h));
    }
    *(uint2*)(g_Ahi + i * 4) = uh.u;
    *(uint2*)(g_Alo + i * 4) = ul.u;
}

// =====================================================================
// Kernel B: transpose W [4096,1024] -> Wt hi/lo [1024,4096] bf16
// =====================================================================
__global__ void convert_W(const float* __restrict__ W)
{
    __shared__ __nv_bfloat16 th[32][33];
    __shared__ __nv_bfloat16 tl[32][33];
    const int k0 = blockIdx.x * 32, n0 = blockIdx.y * 32;
    const int tx = threadIdx.x, ty = threadIdx.y;   // (32, 8)
    #pragma unroll
    for (int i = 0; i < 4; i++) {
        const int kk = ty + i * 8;
        float x = W[(size_t)(k0 + kk) * D_EMB + n0 + tx];
        __nv_bfloat16 h = __float2bfloat16_rn(x);
        th[kk][tx] = h;
        tl[kk][tx] = __float2bfloat16_rn(x - __bfloat162float(h));
    }
    __syncthreads();
    #pragma unroll
    for (int i = 0; i < 4; i++) {
        const int nn = ty + i * 8;
        g_Wthi[(size_t)(n0 + nn) * F_IN + k0 + tx] = th[tx][nn];
        g_Wtlo[(size_t)(n0 + nn) * F_IN + k0 + tx] = tl[tx][nn];
    }
}

// =====================================================================
// Kernel C: bf16x3 tensor-core GEMM. 128x256 tile, 8 warps (64x64),
// K-chunk 64 (half the barrier/boundary count of GK=32), 2-stage
// cp.async double buffer. Row stride 144B = 9x16B (odd multiple ->
// ldmatrix conflict-free).
// =====================================================================
#define GM 128
#define GN 256
#define GK 64
#define NCH (F_IN / GK)          // 64
#define ROWB 144                 // 64 bf16 (128B) + 16B pad
#define SA_HI 0
#define SA_LO (GM * ROWB)                      // 18432
#define SB_HI (2 * GM * ROWB)                  // 36864
#define STAGE (2 * GM * ROWB + 2 * GN * ROWB)  // 110592
#define NSTAGE 2
#define GEMM_SMEM (NSTAGE * STAGE)             // 221184

__device__ __forceinline__ void copy_chunk(uint32_t sb, int blockRow, int blockCol,
                                           int c, int tid)
{
    const size_t kc = (size_t)c * GK;
    // A hi+lo: 128 rows x 8 segs x 2 arrays = 2048 x 16B, 256 thr -> 8 iters
    #pragma unroll
    for (int i = 0; i < 8; i++) {
        const int id  = tid + i * 256;
        const int arr = id >> 10;           // 0 hi, 1 lo
        const int rid = (id >> 3) & 127;
        const int seg = id & 7;
        const char* src = (const char*)(arr ? g_Alo : g_Ahi)
                        + ((size_t)(blockRow + rid) * F_IN + kc) * 2 + seg * 16;
        cp_async16(sb + arr * (GM * ROWB) + rid * ROWB + seg * 16, src);
    }
    // B hi+lo: 256 rows x 8 segs x 2 arrays = 4096 x 16B -> 16 iters
    #pragma unroll
    for (int i = 0; i < 16; i++) {
        const int id  = tid + i * 256;
        const int arr = id >> 11;
        const int rid = (id >> 3) & 255;
        const int seg = id & 7;
        const char* src = (const char*)(arr ? g_Wtlo : g_Wthi)
                        + ((size_t)(blockCol + rid) * F_IN + kc) * 2 + seg * 16;
        cp_async16(sb + SB_HI + arr * (GN * ROWB) + rid * ROWB + seg * 16, src);
    }
}

// one full pass over the 64x64 warp tile: 32 HMMA
#define MMA_PASS(ACC, A, B)                                   \
    _Pragma("unroll")                                         \
    for (int mt = 0; mt < 4; mt++) {                          \
        _Pragma("unroll")                                     \
        for (int p = 0; p < 4; p++) {                         \
            mma_bf16(ACC[mt][p * 2 + 0], A[mt], &B[p][0]);    \
            mma_bf16(ACC[mt][p * 2 + 1], A[mt], &B[p][2]);    \
        }                                                     \
    }

__global__ __launch_bounds__(256, 1)
void gemm_bf16x3(const float* __restrict__ bias)
{
    extern __shared__ char smem[];
    const uint32_t sbase = smem_u32(smem);
    const int tid = threadIdx.x;
    const int wid = tid >> 5;
    const int l   = tid & 31;
    const int warpM = wid >> 2;          // 0..1 -> 64-row strip
    const int warpN = wid & 3;           // 0..3 -> 64-col strip
    const int blockRow = blockIdx.y * GM;
    const int blockCol = blockIdx.x * GN;

    const uint32_t aOff = (uint32_t)((warpM * 64 + (l & 15)) * ROWB + (l >> 4) * 16);
    uint32_t bOff[4];
    #pragma unroll
    for (int p = 0; p < 4; p++)
        bOff[p] = (uint32_t)(SB_HI + (warpN * 64 + p * 16 + ((l >> 4) & 1) * 8 + (l & 7)) * ROWB
                             + ((l >> 3) & 1) * 16);

    float acc[4][8][4];
    #pragma unroll
    for (int mt = 0; mt < 4; mt++)
        #pragma unroll
        for (int nt = 0; nt < 8; nt++)
            #pragma unroll
            for (int r = 0; r < 4; r++) acc[mt][nt][r] = 0.f;

    // prologue: chunk 0 -> stage 0
    copy_chunk(sbase, blockRow, blockCol, 0, tid);
    cp_commit();

    for (int c = 0; c < NCH; c++) {
        cp_wait0();            // chunk c fully copied (only group possibly live)
        __syncthreads();       // copies visible to all; compute c-1 finished
        // stage (c+1)&1 was used by compute c-1 -> free now; start chunk c+1
        if (c + 1 < NCH)
            copy_chunk(sbase + (uint32_t)((c + 1) & 1) * STAGE, blockRow, blockCol, c + 1, tid);
        cp_commit();

        const uint32_t st = sbase + (uint32_t)(c & 1) * STAGE;
        #pragma unroll
        for (int ks = 0; ks < 4; ks++) {
            const uint32_t kb = ks * 32;   // 16 bf16 = 32B per k-step
            uint32_t aH[4][4], aL[4][4], bH[4][4], bL[4][4];

            #pragma unroll
            for (int mt = 0; mt < 4; mt++) ldmx4(aH[mt], st + aOff + mt * (16 * ROWB) + kb);
            #pragma unroll
            for (int p = 0; p < 4; p++)   ldmx4(bH[p], st + bOff[p] + kb);

            // pass 1: hi * hi
            MMA_PASS(acc, aH, bH);

            // pass 2: lo * hi
            #pragma unroll
            for (int mt = 0; mt < 4; mt++) ldmx4(aL[mt], st + aOff + SA_LO + mt * (16 * ROWB) + kb);
            MMA_PASS(acc, aL, bH);

            // pass 3: hi * lo
            #pragma unroll
            for (int p = 0; p < 4; p++)   ldmx4(bL[p], st + bOff[p] + (GN * ROWB) + kb);
            MMA_PASS(acc, aH, bL);
        }
    }

    // epilogue: + bias, store fp32
    #pragma unroll
    for (int mt = 0; mt < 4; mt++) {
        const int r0 = blockRow + warpM * 64 + mt * 16 + (l >> 2);
        #pragma unroll
        for (int nt = 0; nt < 8; nt++) {
            const int col = blockCol + warpN * 64 + nt * 8 + (l & 3) * 2;
            const float b0 = bias[col], b1 = bias[col + 1];
            float2 v0 = make_float2(acc[mt][nt][0] + b0, acc[mt][nt][1] + b1);
            float2 v1 = make_float2(acc[mt][nt][2] + b0, acc[mt][nt][3] + b1);
            *(float2*)(g_Z + (size_t)r0 * D_EMB + col)       = v0;
            *(float2*)(g_Z + (size_t)(r0 + 8) * D_EMB + col) = v1;
        }
    }
}

// =====================================================================
// Kernel E: prototypes (lower median + mean) with inline stable order
// scan (warp 0 ballot compaction), class stats. One block per class.
// =====================================================================
__global__ __launch_bounds__(256)
void proto_kernel(const int* __restrict__ labels)
{
    const int c   = blockIdx.x;
    const int tid = threadIdx.x;
    const int l   = tid & 31;
    __shared__ float s_sum[256], s_sum2[256];
    __shared__ int   s_idx[K_SHOT];

    if (c < N_WAY && tid < 32) {
        int base = 0;
        for (int i0 = 0; i0 < N_SUPPORT; i0 += 32) {
            const int i = i0 + l;
            const bool match = (i < N_SUPPORT) && (labels[i] == c);
            const unsigned m = __ballot_sync(0xFFFFFFFFu, match);
            if (match) {
                const int pos = base + __popc(m & ((1u << l) - 1u));
                if (pos < K_SHOT) s_idx[pos] = i;
            }
            base += __popc(m);
        }
    }
    __syncthreads();

    float psum = 0.f, psum2 = 0.f;
    if (c < N_WAY) {
        int idx[K_SHOT];
        #pragma unroll
        for (int j = 0; j < K_SHOT; j++) idx[j] = s_idx[j];

        for (int d = tid; d < D_EMB; d += 256) {
            float v[K_SHOT];
            #pragma unroll
            for (int j = 0; j < K_SHOT; j++)
                v[j] = g_Z[(size_t)(N_QUERY + idx[j]) * D_EMB + d];

            float mean = 0.f;
            #pragma unroll
            for (int j = 0; j < K_SHOT; j++) mean += v[j];
            mean *= (1.0f / K_SHOT);

            #pragma unroll
            for (int p = 0; p < K_SHOT - 1; p++)
                #pragma unroll
                for (int q = 0; q < K_SHOT - 1 - p; q++) {
                    float lo = fminf(v[q], v[q + 1]);
                    float hi = fmaxf(v[q], v[q + 1]);
                    v[q] = lo; v[q + 1] = hi;
                }
            const float med = v[(K_SHOT - 1) / 2];
            const float zt  = 0.5f * (med + mean);
            g_proto[(size_t)c * D_EMB + d] = zt;
            psum += zt; psum2 += zt * zt;
        }
    } else {
        for (int d = tid; d < D_EMB; d += 256)
            g_proto[(size_t)c * D_EMB + d] = 0.f;
    }

    s_sum[tid] = psum; s_sum2[tid] = psum2;
    __syncthreads();
    for (int s = 128; s > 0; s >>= 1) {
        if (tid < s) { s_sum[tid] += s_sum[tid + s]; s_sum2[tid] += s_sum2[tid + s]; }
        __syncthreads();
    }
    if (tid == 0 && c < N_WAY) { g_ps[c] = s_sum[0]; g_p2[c] = s_sum2[0]; }
}

// =====================================================================
// Kernel F: per-query-row sum / sum-of-squares — warp per row (fp32)
// =====================================================================
__global__ __launch_bounds__(256)
void qstats_kernel()
{
    const int warp = (blockIdx.x * blockDim.x + threadIdx.x) >> 5;
    const int l    = threadIdx.x & 31;
    if (warp >= N_QUERY) return;
    const float* z = g_Z + (size_t)warp * D_EMB;
    float s = 0.f, s2 = 0.f;
    #pragma unroll
    for (int i = 0; i < 8; i++) {
        float4 v = *(const float4*)(z + (l + i * 32) * 4);
        s  += v.x + v.y + v.z + v.w;
        s2 += v.x * v.x + v.y * v.y + v.z * v.z + v.w * v.w;
    }
    #pragma unroll
    for (int off = 16; off > 0; off >>= 1) {
        s  += __shfl_xor_sync(0xFFFFFFFFu, s,  off);
        s2 += __shfl_xor_sync(0xFFFFFFFFu, s2, off);
    }
    if (l == 0) { g_qs[warp] = s; g_q2[warp] = s2; }
}

// =====================================================================
// Kernel G: distance matrix (SIMT) with fused PairwiseDistance-eps
// =====================================================================
#define DBM 64
#define DBN 128
#define DBK 16
#define DTM 4
#define DTN 8

__global__ __launch_bounds__(256)
void dist_kernel(float* __restrict__ out)
{
    __shared__ float As2[DBK][DBM];
    __shared__ float Bs2[DBK][DBN];

    const int tid      = threadIdx.x;
    const int blockRow = blockIdx.x * DBM;

    const int aRow = tid >> 2;
    const int aCol = (tid & 3) << 2;
    const int tr = (tid >> 4) * DTM;
    const int tc = (tid & 15) * DTN;

    float acc[DTM][DTN] = {};

    const int nk = D_EMB / DBK;
    for (int kt = 0; kt < nk; kt++) {
        const int kc = kt * DBK;
        {
            float4 a = *(const float4*)(g_Z + (size_t)(blockRow + aRow) * D_EMB + kc + aCol);
            As2[aCol + 0][aRow] = a.x; As2[aCol + 1][aRow] = a.y;
            As2[aCol + 2][aRow] = a.z; As2[aCol + 3][aRow] = a.w;
        }
        #pragma unroll
        for (int s = 0; s < 2; s++) {
            const int idx = tid + s * 256;
            const int n   = idx >> 2;
            const int k4  = (idx & 3) << 2;
            float4 p = *(const float4*)(g_proto + (size_t)n * D_EMB + kc + k4);
            Bs2[k4 + 0][n] = p.x; Bs2[k4 + 1][n] = p.y;
            Bs2[k4 + 2][n] = p.z; Bs2[k4 + 3][n] = p.w;
        }
        __syncthreads();

        #pragma unroll
        for (int k = 0; k < DBK; k++) {
            float ar[DTM], br[DTN];
            *(float4*)&ar[0] = *(const float4*)&As2[k][tr];
            *(float4*)&br[0] = *(const float4*)&Bs2[k][tc];
            *(float4*)&br[4] = *(const float4*)&Bs2[k][tc + 4];
            #pragma unroll
            for (int i = 0; i < DTM; i++)
                #pragma unroll
                for (int j = 0; j < DTN; j++)
                    acc[i][j] += ar[i] * br[j];
        }
        __syncthreads();
    }

    const float deps2 = (float)D_EMB * EPS_F * EPS_F;
    #pragma unroll
    for (int i = 0; i < DTM; i++) {
        const int r = blockRow + tr + i;
        const float q2v = g_q2[r];
        const float qsv = g_qs[r];
        #pragma unroll
        for (int j = 0; j < DTN; j++) {
            const int c = tc + j;
            if (c < N_WAY) {
                float sq = q2v + g_p2[c] - 2.0f * acc[i][j]
                         + 2.0f * EPS_F * (qsv - g_ps[c]) + deps2;
                out[(size_t)r * N_WAY + c] = -sqrtf(fmaxf(sq, 0.0f));
            }
        }
    }
}

// =====================================================================
// launch
// =====================================================================
extern "C" void kernel_launch(void* const* d_in, const int* in_sizes, int n_in,
                              void* d_out, int out_size)
{
    const float* support = (const float*)d_in[0];
    const int*   labels  = (const int*)  d_in[1];
    const float* query   = (const float*)d_in[2];
    const float* W       = (const float*)d_in[3];
    const float* b       = (const float*)d_in[4];
    float*       out     = (float*)d_out;

    cudaFuncSetAttribute(gemm_bf16x3,
                         cudaFuncAttributeMaxDynamicSharedMemorySize, GEMM_SMEM);

    {
        const size_t total = (size_t)M_TOT * F_IN / 4;
        convert_A<<<(unsigned)((total + 255) / 256), 256>>>(query, support);
    }
    convert_W<<<dim3(F_IN / 32, D_EMB / 32), dim3(32, 8)>>>(W);

    gemm_bf16x3<<<dim3(D_EMB / GN, M_TOT / GM), 256, GEMM_SMEM>>>(b);

    proto_kernel<<<128, 256>>>(labels);
    qstats_kernel<<<N_QUERY / 8, 256>>>();
    dist_kernel<<<N_QUERY / DBM, 256>>>(out);
}